// round 14
// baseline (speedup 1.0000x reference)
#include <cuda_runtime.h>
#include <cuda_fp16.h>
#include <cstdint>

#define D 128
#define PITCH 136              // fp16 elems per smem row = 272 B
#define NTHREADS 512           // 12 consumer warps + 4 producer warps
#define TROWS 96               // CTA tile rows

static const int MAX_E = 800000;
static const int MAX_N = 50000;

// P/Q fp16, permuted per 64-col block: pos = qid*16 + ni*2 + t holds
// col = block*64 + ni*8 + qid*2 + t. Edge kernel gathers a_w inverse-permuted.
// g_M16: fp16 copy of M (row-major), written by producers.
__device__ __align__(16) __half g_P[(size_t)MAX_E * D];    // 204.8 MB
__device__ __align__(16) __half g_Q[(size_t)MAX_E * D];    // 204.8 MB
__device__ __align__(16) __half g_M16[(size_t)MAX_E * D];  // 204.8 MB
__device__ float g_h[MAX_E];
__device__ float g_denom[MAX_N];

// SMEM layout (byte offsets): A16 double buffer + W + bias
static constexpr int SM_A0   = 0;                          // 96 x 272 B
static constexpr int SM_A1   = SM_A0 + TROWS * 272;        // 26112
static constexpr int SM_W    = SM_A1 + TROWS * 272;        // 52224, 256 x 272 B
static constexpr int SM_BIAS = SM_W + 256 * 272;           // 121856
static constexpr int SM_TOTAL = SM_BIAS + 1024;            // 122880

// ---------------------------------------------------------------------------
__device__ __forceinline__ void mma16816(float c[4], const uint32_t a[4],
                                         const uint32_t b0, const uint32_t b1) {
    asm volatile(
        "mma.sync.aligned.m16n8k16.row.col.f32.f16.f16.f32 "
        "{%0,%1,%2,%3}, {%4,%5,%6,%7}, {%8,%9}, {%0,%1,%2,%3};"
        : "+f"(c[0]), "+f"(c[1]), "+f"(c[2]), "+f"(c[3])
        : "r"(a[0]), "r"(a[1]), "r"(a[2]), "r"(a[3]), "r"(b0), "r"(b1));
}
__device__ __forceinline__ void ldmx4(uint32_t r[4], uint32_t addr) {
    asm volatile("ldmatrix.sync.aligned.m8n8.x4.shared.b16 {%0,%1,%2,%3}, [%4];"
                 : "=r"(r[0]), "=r"(r[1]), "=r"(r[2]), "=r"(r[3]) : "r"(addr));
}
// Named-barrier helpers (count is TOTAL arrivals incl. syncing threads)
__device__ __forceinline__ void bar_arrive(int id) {
    asm volatile("bar.arrive %0, %1;" :: "r"(id), "r"(NTHREADS) : "memory");
}
__device__ __forceinline__ void bar_wait(int id) {
    asm volatile("bar.sync %0, %1;" :: "r"(id), "r"(NTHREADS) : "memory");
}

// ---------------------------------------------------------------------------
// K1: warp-specialized fp16 GEMM. Tile [96 x 256] = M @ [W0;W1]^T + b.
// Warps 0-11 consume (MMA + epilogue to g_P/g_Q); warps 12-15 produce
// (LDG fp32 -> cvt fp16 -> STS A16[buf], STG g_M16). Double-buffered A16,
// named-barrier FULL/EMPTY handshake, no __syncthreads in steady state.
// ---------------------------------------------------------------------------
__global__ __launch_bounds__(NTHREADS, 1) void gemm_ws(
    const float* __restrict__ M,
    const float* __restrict__ W0, const float* __restrict__ b0,
    const float* __restrict__ W1, const float* __restrict__ b1,
    float* __restrict__ out, int outN,
    int E, int numTiles)
{
    extern __shared__ char sm[];
    __half* sW   = (__half*)(sm + SM_W);
    float*  sBias = (float*)(sm + SM_BIAS);
    const uint32_t smBase = (uint32_t)(uint64_t)__cvta_generic_to_shared(sm);

    const int tid  = threadIdx.x;
    const int wid  = tid >> 5;
    const int lane = tid & 31;

    // --- Prologue (all 512 threads): zero out/denom, convert W, bias
    {
        int gstride = gridDim.x * NTHREADS;
        int g0 = blockIdx.x * NTHREADS + tid;
        float4 z4 = make_float4(0.f, 0.f, 0.f, 0.f);
        int n4 = outN >> 2;
        for (int i = g0; i < n4; i += gstride) ((float4*)out)[i] = z4;
        for (int i = g0; i < MAX_N; i += gstride) g_denom[i] = 0.0f;
    }
    for (int i = tid; i < 256 * D; i += NTHREADS) {
        int n = i >> 7, k = i & 127;
        float w = (n < 128) ? W0[n * D + k] : W1[(n - 128) * D + k];
        sW[n * PITCH + k] = __float2half_rn(w);
    }
    if (tid < 256) sBias[tid] = (tid < 128) ? b0[tid] : b1[tid - 128];
    __syncthreads();   // last full-block sync

    // Barrier ids: FULL[b] = 1+b (producers arrive, consumers wait)
    //              EMPTY[b] = 3+b (consumers arrive, producers wait)

    if (wid >= 12) {
        // ===================== PRODUCER (warps 12-15) =====================
        const int p = tid - 384;        // 0..127
        int iter = 0;
        for (int tile = blockIdx.x; tile < numTiles; tile += gridDim.x, iter++) {
            const int b = iter & 1;
            if (iter >= 2) bar_wait(3 + b);          // A16[b] free
            __half* sA = (__half*)(sm + (b ? SM_A1 : SM_A0));
            long row0 = (long)tile * TROWS;

            // 96 rows x 128 cols fp32 = 3072 float4; 24 per producer thread
            #pragma unroll
            for (int i = 0; i < 24; i++) {
                int idx4 = p + i * 128;
                int r  = idx4 >> 5;
                int c  = (idx4 & 31) * 4;
                long grow = row0 + r;
                float4 v;
                if (grow < (long)E) v = *(const float4*)(M + grow * D + c);
                else v = make_float4(0.f, 0.f, 0.f, 0.f);
                __half2 h01 = __floats2half2_rn(v.x, v.y);
                __half2 h23 = __floats2half2_rn(v.z, v.w);
                uint2 hv = make_uint2(*(uint32_t*)&h01, *(uint32_t*)&h23);
                *(uint2*)(sA + r * PITCH + c) = hv;
                if (grow < (long)E)
                    *(uint2*)(g_M16 + grow * D + c) = hv;
            }
            bar_arrive(1 + b);                        // A16[b] full
        }
        return;
    }

    // ======================= CONSUMER (warps 0-11) ========================
    const int gid = lane >> 2;
    const int qid = lane & 3;
    const int mr = (wid >> 2) * 32;        // 0 | 32 | 64
    const int nc = (wid & 3) * 64;         // 0 | 64 | 128 | 192
    const int blockQ = (nc >= 128);
    const int blk64  = (nc & 64) ? 1 : 0;

    const int rr = lane & 7;
    const int j  = lane >> 3;
    const uint32_t aOff = (uint32_t)((mr + ((j & 1) << 3) + rr) * 272 + ((j >> 1) << 4));
    const uint32_t aAddr0 = smBase + SM_A0 + aOff;
    const uint32_t aAddr1 = smBase + SM_A1 + aOff;
    uint32_t bAddr[4];
    #pragma unroll
    for (int nip = 0; nip < 4; nip++)
        bAddr[nip] = smBase + SM_W
                   + (uint32_t)((nc + nip * 16 + ((j >> 1) << 3) + rr) * 272
                                + ((j & 1) << 4));

    int iter = 0;
    for (int tile = blockIdx.x; tile < numTiles; tile += gridDim.x, iter++) {
        const int b = iter & 1;
        bar_wait(1 + b);                              // A16[b] full
        const uint32_t aBase = b ? aAddr1 : aAddr0;
        long row0 = (long)tile * TROWS;

        float acc[2][8][4];
        #pragma unroll
        for (int mi = 0; mi < 2; mi++)
            #pragma unroll
            for (int ni = 0; ni < 8; ni++)
                #pragma unroll
                for (int r = 0; r < 4; r++) acc[mi][ni][r] = 0.0f;

        #pragma unroll
        for (int ks = 0; ks < 8; ks++) {
            const uint32_t ko = (uint32_t)(ks * 32);
            uint32_t a[2][4];
            ldmx4(a[0], aBase + ko);
            ldmx4(a[1], aBase + 16 * 272 + ko);
            uint32_t bb[4][4];
            #pragma unroll
            for (int nip = 0; nip < 4; nip++)
                ldmx4(bb[nip], bAddr[nip] + ko);

            #pragma unroll
            for (int mi = 0; mi < 2; mi++)
                #pragma unroll
                for (int nip = 0; nip < 4; nip++) {
                    mma16816(acc[mi][nip * 2 + 0], a[mi], bb[nip][0], bb[nip][1]);
                    mma16816(acc[mi][nip * 2 + 1], a[mi], bb[nip][2], bb[nip][3]);
                }
        }
        bar_arrive(3 + b);                            // A16[b] free

        // Epilogue: + bias, permuted wide stores (registers only)
        __half* gBase = blockQ ? g_Q : g_P;
        #pragma unroll
        for (int mi = 0; mi < 2; mi++) {
            long rowA = row0 + mr + mi * 16 + gid;
            long rowB = rowA + 8;
            __half2 hA[8], hB[8];
            #pragma unroll
            for (int ni = 0; ni < 8; ni++) {
                int col = nc + ni * 8 + qid * 2;
                float bx = sBias[col], by = sBias[col + 1];
                hA[ni] = __floats2half2_rn(acc[mi][ni][0] + bx, acc[mi][ni][1] + by);
                hB[ni] = __floats2half2_rn(acc[mi][ni][2] + bx, acc[mi][ni][3] + by);
            }
            if (rowA < (long)E) {
                __half* dst = gBase + rowA * D + blk64 * 64 + qid * 16;
                ((uint4*)dst)[0] = make_uint4(
                    *(uint32_t*)&hA[0], *(uint32_t*)&hA[1],
                    *(uint32_t*)&hA[2], *(uint32_t*)&hA[3]);
                ((uint4*)dst)[1] = make_uint4(
                    *(uint32_t*)&hA[4], *(uint32_t*)&hA[5],
                    *(uint32_t*)&hA[6], *(uint32_t*)&hA[7]);
            }
            if (rowB < (long)E) {
                __half* dst = gBase + rowB * D + blk64 * 64 + qid * 16;
                ((uint4*)dst)[0] = make_uint4(
                    *(uint32_t*)&hB[0], *(uint32_t*)&hB[1],
                    *(uint32_t*)&hB[2], *(uint32_t*)&hB[3]);
                ((uint4*)dst)[1] = make_uint4(
                    *(uint32_t*)&hB[4], *(uint32_t*)&hB[5],
                    *(uint32_t*)&hB[6], *(uint32_t*)&hB[7]);
            }
        }
    }
}

// ---------------------------------------------------------------------------
// K2: fused edge pass, 4 edges per warp. P/Q permuted; a_w gathered at
// inverse-permuted columns. M read as fp16 from g_M16.
// ---------------------------------------------------------------------------
__global__ __launch_bounds__(256) void edge_kernel(
    const int* __restrict__ rev, const int* __restrict__ dest,
    const float* __restrict__ a_w, const float* __restrict__ a_b,
    float* __restrict__ out, int E)
{
    const int warp = (blockIdx.x * blockDim.x + threadIdx.x) >> 5;
    const int lane = threadIdx.x & 31;
    const long e0 = (long)warp * 4;
    if (e0 >= E) return;

    const int p0   = lane * 4;
    const int blk  = p0 >> 6;
    const int bb   = p0 & 63;
    const int c0   = blk * 64 + ((bb & 15) >> 1) * 8 + (bb >> 4) * 2;
    const float aw0 = a_w[c0],     aw1 = a_w[c0 + 1];
    const float aw2 = a_w[c0 + 8], aw3 = a_w[c0 + 9];

    int4 rv, dv;
    if (lane == 0) {
        rv = *(const int4*)(rev + e0);
        dv = *(const int4*)(dest + e0);
    }
    rv.x = __shfl_sync(0xffffffffu, rv.x, 0); rv.y = __shfl_sync(0xffffffffu, rv.y, 0);
    rv.z = __shfl_sync(0xffffffffu, rv.z, 0); rv.w = __shfl_sync(0xffffffffu, rv.w, 0);
    dv.x = __shfl_sync(0xffffffffu, dv.x, 0); dv.y = __shfl_sync(0xffffffffu, dv.y, 0);
    dv.z = __shfl_sync(0xffffffffu, dv.z, 0); dv.w = __shfl_sync(0xffffffffu, dv.w, 0);
    const int re[4] = {rv.x, rv.y, rv.z, rv.w};
    const int dd[4] = {dv.x, dv.y, dv.z, dv.w};

    const int nE = (int)(((long)E - e0) < 4 ? ((long)E - e0) : 4);

    uint2 pv[4], qv[4], mv[4];
    #pragma unroll
    for (int i = 0; i < 4; i++) {
        long e = (i < nE) ? (e0 + i) : e0;
        int r  = (i < nE) ? re[i] : re[0];
        pv[i] = ((const uint2*)g_P)[e * 32 + lane];
        qv[i] = ((const uint2*)g_Q)[(long)r * 32 + lane];
        mv[i] = ((const uint2*)g_M16)[e * 32 + lane];
    }
    const float ab = a_b[0];

    float part[4];
    #pragma unroll
    for (int i = 0; i < 4; i++) {
        float2 p01 = __half22float2(*(const __half2*)&pv[i].x);
        float2 p23 = __half22float2(*(const __half2*)&pv[i].y);
        float2 q01 = __half22float2(*(const __half2*)&qv[i].x);
        float2 q23 = __half22float2(*(const __half2*)&qv[i].y);
        float zx = p01.x + q01.x; zx = zx > 0.f ? zx : 0.2f * zx;
        float zy = p01.y + q01.y; zy = zy > 0.f ? zy : 0.2f * zy;
        float zz = p23.x + q23.x; zz = zz > 0.f ? zz : 0.2f * zz;
        float zw = p23.y + q23.y; zw = zw > 0.f ? zw : 0.2f * zw;
        part[i] = aw0 * zx + aw1 * zy + aw2 * zz + aw3 * zw;
    }

    #pragma unroll
    for (int off = 16; off; off >>= 1) {
        #pragma unroll
        for (int i = 0; i < 4; i++)
            part[i] += __shfl_xor_sync(0xffffffffu, part[i], off);
    }

    float h[4];
    #pragma unroll
    for (int i = 0; i < 4; i++) h[i] = expf(part[i] + ab);

    if (lane == 0)           { g_h[e0 + 0] = h[0]; atomicAdd(&g_denom[dd[0]], h[0]); }
    if (lane == 1 && nE > 1) { g_h[e0 + 1] = h[1]; atomicAdd(&g_denom[dd[1]], h[1]); }
    if (lane == 2 && nE > 2) { g_h[e0 + 2] = h[2]; atomicAdd(&g_denom[dd[2]], h[2]); }
    if (lane == 3 && nE > 3) { g_h[e0 + 3] = h[3]; atomicAdd(&g_denom[dd[3]], h[3]); }

    #pragma unroll
    for (int i = 0; i < 4; i++) {
        if (i < nE) {
            float2 m01 = __half22float2(*(const __half2*)&mv[i].x);
            float2 m23 = __half22float2(*(const __half2*)&mv[i].y);
            float* o = out + (long)dd[i] * D + lane * 4;
            asm volatile("red.global.add.v4.f32 [%0], {%1, %2, %3, %4};"
                         :: "l"(o), "f"(h[i] * m01.x), "f"(h[i] * m01.y),
                            "f"(h[i] * m23.x), "f"(h[i] * m23.y)
                         : "memory");
        }
    }
}

// ---------------------------------------------------------------------------
// K3: normalize out rows by denom and compute alpha = h / denom[dest].
// ---------------------------------------------------------------------------
__global__ __launch_bounds__(256) void normalize_kernel(
    const int* __restrict__ dest,
    float* __restrict__ out, float* __restrict__ alpha_out, int N, int E)
{
    int i = blockIdx.x * blockDim.x + threadIdx.x;
    int nOut = N * 32;
    if (i < nOut) {
        int n = i >> 5;
        float inv = 1.0f / g_denom[n];
        float4* p = (float4*)out + i;
        float4 v = *p;
        v.x *= inv; v.y *= inv; v.z *= inv; v.w *= inv;
        *p = v;
    } else if (i < nOut + E) {
        int e = i - nOut;
        alpha_out[e] = g_h[e] / g_denom[dest[e]];
    }
}

// ---------------------------------------------------------------------------
extern "C" void kernel_launch(void* const* d_in, const int* in_sizes, int n_in,
                              void* d_out, int out_size)
{
    const float* M    = (const float*)d_in[0];
    const int*   dest = (const int*)d_in[1];
    const int*   rev  = (const int*)d_in[2];
    int base = (n_in >= 10) ? 4 : 3;
    const float* W0   = (const float*)d_in[base + 0];
    const float* b0   = (const float*)d_in[base + 1];
    const float* W1   = (const float*)d_in[base + 2];
    const float* b1   = (const float*)d_in[base + 3];
    const float* a_w  = (const float*)d_in[base + 4];
    const float* a_b  = (const float*)d_in[base + 5];

    int E = in_sizes[1];
    int N = (out_size - E) / D;

    float* out   = (float*)d_out;
    float* alpha = (float*)d_out + (long)N * D;

    cudaFuncSetAttribute(gemm_ws,
        cudaFuncAttributeMaxDynamicSharedMemorySize, SM_TOTAL);

    // K1: warp-specialized GEMM (zeroes out[]/denom; writes P, Q, M16)
    int numTiles = (E + TROWS - 1) / TROWS;
    gemm_ws<<<148, NTHREADS, SM_TOTAL>>>(M, W0, b0, W1, b1, out, N * D, E, numTiles);

    // K2: fused edge pass, 4 edges/warp
    long warps = ((long)E + 3) / 4;
    int blocks = (int)((warps + 7) / 8);
    edge_kernel<<<blocks, 256>>>(rev, dest, a_w, a_b, out, E);

    // K3: normalize + alpha
    int totWork = N * 32 + E;
    normalize_kernel<<<(totWork + 255) / 256, 256>>>(dest, out, alpha, N, E);
}

// round 15
// speedup vs baseline: 1.2770x; 1.2770x over previous
#include <cuda_runtime.h>
#include <cuda_fp16.h>
#include <cstdint>

#define D 128
#define PITCH 136              // fp16 elems per smem row = 272 B
#define NTHREADS 512

static const int MAX_E = 800000;
static const int MAX_N = 50000;

// P/Q fp16, permuted per 64-col block: pos = qid*16 + ni*2 + t holds
// col = block*64 + ni*8 + qid*2 + t. Edge kernel gathers a_w inverse-permuted.
// g_M16: fp16 copy of M (row-major), written by gemm, read by edge scatter.
__device__ __align__(16) __half g_P[(size_t)MAX_E * D];    // 204.8 MB
__device__ __align__(16) __half g_Q[(size_t)MAX_E * D];    // 204.8 MB
__device__ __align__(16) __half g_M16[(size_t)MAX_E * D];  // 204.8 MB
__device__ float g_h[MAX_E];
__device__ float g_denom[MAX_N];

// SMEM layout (byte offsets)
static constexpr int SM_RAW  = 0;                         // 128 x 512 B raw fp32 A
static constexpr int SM_A0   = 65536;                     // 128 x 272 B fp16 A buf0
static constexpr int SM_A1   = SM_A0 + 128 * 272;         // buf1
static constexpr int SM_W    = SM_A1 + 128 * 272;         // 256 x 272 B
static constexpr int SM_BIAS = SM_W + 256 * 272;          // 256 fp32
static constexpr int SM_TOTAL = SM_BIAS + 1024;           // 205824

// ---------------------------------------------------------------------------
__device__ __forceinline__ void mma16816(float c[4], const uint32_t a[4],
                                         const uint32_t b0, const uint32_t b1) {
    asm volatile(
        "mma.sync.aligned.m16n8k16.row.col.f32.f16.f16.f32 "
        "{%0,%1,%2,%3}, {%4,%5,%6,%7}, {%8,%9}, {%0,%1,%2,%3};"
        : "+f"(c[0]), "+f"(c[1]), "+f"(c[2]), "+f"(c[3])
        : "r"(a[0]), "r"(a[1]), "r"(a[2]), "r"(a[3]), "r"(b0), "r"(b1));
}
__device__ __forceinline__ void ldmx4(uint32_t r[4], uint32_t addr) {
    asm volatile("ldmatrix.sync.aligned.m8n8.x4.shared.b16 {%0,%1,%2,%3}, [%4];"
                 : "=r"(r[0]), "=r"(r[1]), "=r"(r[2]), "=r"(r[3]) : "r"(addr));
}
__device__ __forceinline__ void cp16(uint32_t dst_smem, const void* src, int srcBytes) {
    asm volatile("cp.async.cg.shared.global [%0], [%1], 16, %2;"
                 :: "r"(dst_smem), "l"(src), "r"(srcBytes) : "memory");
}
__device__ __forceinline__ void cp_commit() {
    asm volatile("cp.async.commit_group;" ::: "memory");
}
__device__ __forceinline__ void cp_wait0() {
    asm volatile("cp.async.wait_group 0;" ::: "memory");
}
// Group-local barrier: 4 warps (128 threads) of m-group g sync on id 1+g.
__device__ __forceinline__ void gbar(int g) {
    asm volatile("bar.sync %0, 128;" :: "r"(1 + g) : "memory");
}

// ---------------------------------------------------------------------------
// K1: fp16 mma.sync GEMM. Tile [128 x 256] = M @ [W0;W1]^T + b.
// 16 warps = 4 m-groups x 4 n-warps. Each m-group (4 warps, 128 threads) owns
// A-rows 32g..32g+31 end-to-end: cp.async quarter, convert quarter, ldmatrix
// quarter, epilogue rows, g_M16 rows. Groups synchronize ONLY among
// themselves (named barrier 1+g), so the 4 pipelines drift independently —
// no CTA-wide barrier in the tile loop.
// ---------------------------------------------------------------------------
__global__ __launch_bounds__(NTHREADS, 1) void gemm_mma(
    const float* __restrict__ M,
    const float* __restrict__ W0, const float* __restrict__ b0,
    const float* __restrict__ W1, const float* __restrict__ b1,
    float* __restrict__ out, int outN,
    int E, int numTiles)
{
    extern __shared__ char sm[];
    float*  sRaw = (float*)(sm + SM_RAW);
    __half* sW   = (__half*)(sm + SM_W);
    float*  sBias = (float*)(sm + SM_BIAS);
    const uint32_t smBase = (uint32_t)(uint64_t)__cvta_generic_to_shared(sm);
    const uint32_t rawBase = smBase + SM_RAW;

    const int tid  = threadIdx.x;
    const int wid  = tid >> 5;
    const int lane = tid & 31;
    const int gid  = lane >> 2;
    const int qid  = lane & 3;
    const int g    = wid >> 2;        // m-group 0..3
    const int pt   = tid & 127;       // thread index within group

    // Prologue cp.async: each group copies its 32 rows of the first tile.
    // Thread pt handles chunks idx = pt + i*128 (i<8); chunk -> (r', c).
    {
        long row0 = (long)blockIdx.x * 128;
        if (blockIdx.x < numTiles) {
            #pragma unroll
            for (int i = 0; i < 8; i++) {
                int idx = pt + i * 128;              // 0..1023 within group
                int rp  = idx >> 5;                  // row within group
                int c4  = (idx & 31);                // float4 col
                int row = g * 32 + rp;
                long grow = row0 + row;
                int sz = (grow < (long)E) ? 16 : 0;
                cp16(rawBase + (row * 32 + c4) * 16,
                     (const char*)M + (grow * D + c4 * 4) * 4, sz);
            }
        }
        cp_commit();
    }

    // Zero out[] and g_denom[]
    {
        int gstride = gridDim.x * NTHREADS;
        int g0 = blockIdx.x * NTHREADS + tid;
        float4 z4 = make_float4(0.f, 0.f, 0.f, 0.f);
        int n4 = outN >> 2;
        for (int i = g0; i < n4; i += gstride) ((float4*)out)[i] = z4;
        for (int i = g0; i < MAX_N; i += gstride) g_denom[i] = 0.0f;
    }

    // Convert W once
    for (int i = tid; i < 256 * D; i += NTHREADS) {
        int n = i >> 7, k = i & 127;
        float w = (n < 128) ? W0[n * D + k] : W1[(n - 128) * D + k];
        sW[n * PITCH + k] = __float2half_rn(w);
    }
    if (tid < 256) sBias[tid] = (tid < 128) ? b0[tid] : b1[tid - 128];

    const int mr = g * 32;
    const int nc = (wid & 3) * 64;
    const int blockQ = (nc >= 128);
    const int blk64  = (nc & 64) ? 1 : 0;

    const int rr = lane & 7;
    const int j  = lane >> 3;
    const uint32_t aOff = (uint32_t)((mr + ((j & 1) << 3) + rr) * 272 + ((j >> 1) << 4));
    const uint32_t aAddr0 = smBase + SM_A0 + aOff;
    const uint32_t aAddr1 = smBase + SM_A1 + aOff;
    uint32_t bAddr[4];
    #pragma unroll
    for (int nip = 0; nip < 4; nip++)
        bAddr[nip] = smBase + SM_W
                   + (uint32_t)((nc + nip * 16 + ((j >> 1) << 3) + rr) * 272
                                + ((j & 1) << 4));

    __syncthreads();   // W/bias ready; ONLY CTA-wide barrier

    int buf = 0;
    for (int tile = blockIdx.x; tile < numTiles; tile += gridDim.x) {
        long row0 = (long)tile * 128;
        int next = tile + gridDim.x;
        __half* sA = (__half*)(sm + (buf ? SM_A1 : SM_A0));
        const uint32_t aBase = buf ? aAddr1 : aAddr0;

        cp_wait0();   // this thread's own chunks landed (it converts only those)

        // Convert own chunks raw fp32 -> fp16 into A16[buf]; keep regs for M16
        uint2 hv[8];
        #pragma unroll
        for (int i = 0; i < 8; i++) {
            int idx = pt + i * 128;
            int rp  = idx >> 5;
            int c   = (idx & 31) * 4;
            int row = g * 32 + rp;
            float4 v = *(const float4*)(sRaw + row * 128 + c);
            __half2 h01 = __floats2half2_rn(v.x, v.y);
            __half2 h23 = __floats2half2_rn(v.z, v.w);
            hv[i] = make_uint2(*(uint32_t*)&h01, *(uint32_t*)&h23);
            *(uint2*)(sA + row * PITCH + c) = hv[i];
        }
        gbar(g);   // group's A16[buf] quarter visible; group's raw free;
                   // group's compute of tile-2 (same buf) long done

        // g_M16 stores (off critical path, drain during compute)
        #pragma unroll
        for (int i = 0; i < 8; i++) {
            int idx = pt + i * 128;
            int rp  = idx >> 5;
            int c   = (idx & 31) * 4;
            long grow = row0 + g * 32 + rp;
            if (grow < (long)E)
                *(uint2*)(g_M16 + grow * D + c) = hv[i];
        }

        // Issue cp.async for next tile (group's rows)
        if (next < numTiles) {
            long nrow0 = (long)next * 128;
            #pragma unroll
            for (int i = 0; i < 8; i++) {
                int idx = pt + i * 128;
                int rp  = idx >> 5;
                int c4  = (idx & 31);
                int row = g * 32 + rp;
                long grow = nrow0 + row;
                int sz = (grow < (long)E) ? 16 : 0;
                cp16(rawBase + (row * 32 + c4) * 16,
                     (const char*)M + (grow * D + c4 * 4) * 4, sz);
            }
        }
        cp_commit();

        // Compute: warp tile 32x64 -> acc[2][8][4] (A rows = group's quarter)
        float acc[2][8][4];
        #pragma unroll
        for (int mi = 0; mi < 2; mi++)
            #pragma unroll
            for (int ni = 0; ni < 8; ni++)
                #pragma unroll
                for (int r = 0; r < 4; r++) acc[mi][ni][r] = 0.0f;

        #pragma unroll
        for (int ks = 0; ks < 8; ks++) {
            const uint32_t ko = (uint32_t)(ks * 32);
            uint32_t a[2][4];
            ldmx4(a[0], aBase + ko);
            ldmx4(a[1], aBase + 16 * 272 + ko);
            uint32_t bb[4][4];
            #pragma unroll
            for (int nip = 0; nip < 4; nip++)
                ldmx4(bb[nip], bAddr[nip] + ko);

            #pragma unroll
            for (int mi = 0; mi < 2; mi++)
                #pragma unroll
                for (int nip = 0; nip < 4; nip++) {
                    mma16816(acc[mi][nip * 2 + 0], a[mi], bb[nip][0], bb[nip][1]);
                    mma16816(acc[mi][nip * 2 + 1], a[mi], bb[nip][2], bb[nip][3]);
                }
        }

        // Epilogue: + bias, permuted wide stores
        __half* gBase = blockQ ? g_Q : g_P;
        #pragma unroll
        for (int mi = 0; mi < 2; mi++) {
            long rowA = row0 + mr + mi * 16 + gid;
            long rowB = rowA + 8;
            __half2 hA[8], hB[8];
            #pragma unroll
            for (int ni = 0; ni < 8; ni++) {
                int col = nc + ni * 8 + qid * 2;
                float bx = sBias[col], by = sBias[col + 1];
                hA[ni] = __floats2half2_rn(acc[mi][ni][0] + bx, acc[mi][ni][1] + by);
                hB[ni] = __floats2half2_rn(acc[mi][ni][2] + bx, acc[mi][ni][3] + by);
            }
            if (rowA < (long)E) {
                __half* dst = gBase + rowA * D + blk64 * 64 + qid * 16;
                ((uint4*)dst)[0] = make_uint4(
                    *(uint32_t*)&hA[0], *(uint32_t*)&hA[1],
                    *(uint32_t*)&hA[2], *(uint32_t*)&hA[3]);
                ((uint4*)dst)[1] = make_uint4(
                    *(uint32_t*)&hA[4], *(uint32_t*)&hA[5],
                    *(uint32_t*)&hA[6], *(uint32_t*)&hA[7]);
            }
            if (rowB < (long)E) {
                __half* dst = gBase + rowB * D + blk64 * 64 + qid * 16;
                ((uint4*)dst)[0] = make_uint4(
                    *(uint32_t*)&hB[0], *(uint32_t*)&hB[1],
                    *(uint32_t*)&hB[2], *(uint32_t*)&hB[3]);
                ((uint4*)dst)[1] = make_uint4(
                    *(uint32_t*)&hB[4], *(uint32_t*)&hB[5],
                    *(uint32_t*)&hB[6], *(uint32_t*)&hB[7]);
            }
        }
        buf ^= 1;
    }
}

// ---------------------------------------------------------------------------
// K2: fused edge pass, 4 edges per warp. P/Q permuted; a_w gathered at
// inverse-permuted columns. M read as fp16 from g_M16.
// ---------------------------------------------------------------------------
__global__ __launch_bounds__(256) void edge_kernel(
    const int* __restrict__ rev, const int* __restrict__ dest,
    const float* __restrict__ a_w, const float* __restrict__ a_b,
    float* __restrict__ out, int E)
{
    const int warp = (blockIdx.x * blockDim.x + threadIdx.x) >> 5;
    const int lane = threadIdx.x & 31;
    const long e0 = (long)warp * 4;
    if (e0 >= E) return;

    const int p0   = lane * 4;
    const int blk  = p0 >> 6;
    const int bb   = p0 & 63;
    const int c0   = blk * 64 + ((bb & 15) >> 1) * 8 + (bb >> 4) * 2;
    const float aw0 = a_w[c0],     aw1 = a_w[c0 + 1];
    const float aw2 = a_w[c0 + 8], aw3 = a_w[c0 + 9];

    int4 rv, dv;
    if (lane == 0) {
        rv = *(const int4*)(rev + e0);
        dv = *(const int4*)(dest + e0);
    }
    rv.x = __shfl_sync(0xffffffffu, rv.x, 0); rv.y = __shfl_sync(0xffffffffu, rv.y, 0);
    rv.z = __shfl_sync(0xffffffffu, rv.z, 0); rv.w = __shfl_sync(0xffffffffu, rv.w, 0);
    dv.x = __shfl_sync(0xffffffffu, dv.x, 0); dv.y = __shfl_sync(0xffffffffu, dv.y, 0);
    dv.z = __shfl_sync(0xffffffffu, dv.z, 0); dv.w = __shfl_sync(0xffffffffu, dv.w, 0);
    const int re[4] = {rv.x, rv.y, rv.z, rv.w};
    const int dd[4] = {dv.x, dv.y, dv.z, dv.w};

    const int nE = (int)(((long)E - e0) < 4 ? ((long)E - e0) : 4);

    uint2 pv[4], qv[4], mv[4];
    #pragma unroll
    for (int i = 0; i < 4; i++) {
        long e = (i < nE) ? (e0 + i) : e0;
        int r  = (i < nE) ? re[i] : re[0];
        pv[i] = ((const uint2*)g_P)[e * 32 + lane];
        qv[i] = ((const uint2*)g_Q)[(long)r * 32 + lane];
        mv[i] = ((const uint2*)g_M16)[e * 32 + lane];
    }
    const float ab = a_b[0];

    float part[4];
    #pragma unroll
    for (int i = 0; i < 4; i++) {
        float2 p01 = __half22float2(*(const __half2*)&pv[i].x);
        float2 p23 = __half22float2(*(const __half2*)&pv[i].y);
        float2 q01 = __half22float2(*(const __half2*)&qv[i].x);
        float2 q23 = __half22float2(*(const __half2*)&qv[i].y);
        float zx = p01.x + q01.x; zx = zx > 0.f ? zx : 0.2f * zx;
        float zy = p01.y + q01.y; zy = zy > 0.f ? zy : 0.2f * zy;
        float zz = p23.x + q23.x; zz = zz > 0.f ? zz : 0.2f * zz;
        float zw = p23.y + q23.y; zw = zw > 0.f ? zw : 0.2f * zw;
        part[i] = aw0 * zx + aw1 * zy + aw2 * zz + aw3 * zw;
    }

    #pragma unroll
    for (int off = 16; off; off >>= 1) {
        #pragma unroll
        for (int i = 0; i < 4; i++)
            part[i] += __shfl_xor_sync(0xffffffffu, part[i], off);
    }

    float h[4];
    #pragma unroll
    for (int i = 0; i < 4; i++) h[i] = expf(part[i] + ab);

    if (lane == 0)           { g_h[e0 + 0] = h[0]; atomicAdd(&g_denom[dd[0]], h[0]); }
    if (lane == 1 && nE > 1) { g_h[e0 + 1] = h[1]; atomicAdd(&g_denom[dd[1]], h[1]); }
    if (lane == 2 && nE > 2) { g_h[e0 + 2] = h[2]; atomicAdd(&g_denom[dd[2]], h[2]); }
    if (lane == 3 && nE > 3) { g_h[e0 + 3] = h[3]; atomicAdd(&g_denom[dd[3]], h[3]); }

    #pragma unroll
    for (int i = 0; i < 4; i++) {
        if (i < nE) {
            float2 m01 = __half22float2(*(const __half2*)&mv[i].x);
            float2 m23 = __half22float2(*(const __half2*)&mv[i].y);
            float* o = out + (long)dd[i] * D + lane * 4;
            asm volatile("red.global.add.v4.f32 [%0], {%1, %2, %3, %4};"
                         :: "l"(o), "f"(h[i] * m01.x), "f"(h[i] * m01.y),
                            "f"(h[i] * m23.x), "f"(h[i] * m23.y)
                         : "memory");
        }
    }
}

// ---------------------------------------------------------------------------
// K3: normalize out rows by denom and compute alpha = h / denom[dest].
// ---------------------------------------------------------------------------
__global__ __launch_bounds__(256) void normalize_kernel(
    const int* __restrict__ dest,
    float* __restrict__ out, float* __restrict__ alpha_out, int N, int E)
{
    int i = blockIdx.x * blockDim.x + threadIdx.x;
    int nOut = N * 32;
    if (i < nOut) {
        int n = i >> 5;
        float inv = 1.0f / g_denom[n];
        float4* p = (float4*)out + i;
        float4 v = *p;
        v.x *= inv; v.y *= inv; v.z *= inv; v.w *= inv;
        *p = v;
    } else if (i < nOut + E) {
        int e = i - nOut;
        alpha_out[e] = g_h[e] / g_denom[dest[e]];
    }
}

// ---------------------------------------------------------------------------
extern "C" void kernel_launch(void* const* d_in, const int* in_sizes, int n_in,
                              void* d_out, int out_size)
{
    const float* M    = (const float*)d_in[0];
    const int*   dest = (const int*)d_in[1];
    const int*   rev  = (const int*)d_in[2];
    int base = (n_in >= 10) ? 4 : 3;
    const float* W0   = (const float*)d_in[base + 0];
    const float* b0   = (const float*)d_in[base + 1];
    const float* W1   = (const float*)d_in[base + 2];
    const float* b1   = (const float*)d_in[base + 3];
    const float* a_w  = (const float*)d_in[base + 4];
    const float* a_b  = (const float*)d_in[base + 5];

    int E = in_sizes[1];
    int N = (out_size - E) / D;

    float* out   = (float*)d_out;
    float* alpha = (float*)d_out + (long)N * D;

    cudaFuncSetAttribute(gemm_mma,
        cudaFuncAttributeMaxDynamicSharedMemorySize, SM_TOTAL);

    // K1: GEMM, decoupled m-group pipelines (zeroes out[]/denom; writes P,Q,M16)
    int numTiles = (E + 127) / 128;
    gemm_mma<<<148, NTHREADS, SM_TOTAL>>>(M, W0, b0, W1, b1, out, N * D, E, numTiles);

    // K2: fused edge pass, 4 edges/warp
    long warps = ((long)E + 3) / 4;
    int blocks = (int)((warps + 7) / 8);
    edge_kernel<<<blocks, 256>>>(rev, dest, a_w, a_b, out, E);

    // K3: normalize + alpha
    int totWork = N * 32 + E;
    normalize_kernel<<<(totWork + 255) / 256, 256>>>(dest, out, alpha, N, E);
}